// round 2
// baseline (speedup 1.0000x reference)
#include <cuda_runtime.h>

#define BSZ  2048
#define SEQL 50
#define NP   (BSZ*SEQL)      /* 102400 pairs */
#define ATTD 64
#define HIDD 128
#define G4   512             /* 4*HID gates */
#define FIN  19              /* 6 + 4 + 9 fused input dim */

typedef unsigned long long ull;

/* ---------------- device scratch (no cudaMalloc allowed) ---------------- */
__device__ float  g_ctx[(size_t)NP * ATTD];        /* [s][b][64]  26 MB  */
__device__ float  g_xg [(size_t)NP * G4];          /* [s][b][512] 210 MB */
__device__ float4 g_whh4t[(HIDD/4) * G4];          /* [kq][col] packed W_hh^T, 256KB */

/* ---------------- f32x2 helpers (2 MACs / instr on sm_103a) ------------- */
__device__ __forceinline__ void fma2(ull& d, ull a, ull b){
    asm("fma.rn.f32x2 %0, %1, %2, %0;" : "+l"(d) : "l"(a), "l"(b));
}
__device__ __forceinline__ float2 unpk(ull v){
    float2 r; asm("mov.b64 {%0, %1}, %2;" : "=f"(r.x), "=f"(r.y) : "l"(v)); return r;
}
__device__ __forceinline__ float hsum2(ull v){ float2 f = unpk(v); return f.x + f.y; }
__device__ __forceinline__ float sigm(float x){ return 1.f/(1.f + __expf(-x)); }
__device__ __forceinline__ float tanhfast(float x){ return 1.f - 2.f/(__expf(2.f*x) + 1.f); }

/* ============ kernel 0: transpose+pack W_hh -> [kq][col] float4 ========= */
__global__ void k_pack(const float* __restrict__ Whh){
    int t = threadIdx.x, kq = blockIdx.x;             /* <<<32,512>>> */
    g_whh4t[kq*G4 + t] = make_float4(Whh[t*HIDD + 4*kq],   Whh[t*HIDD + 4*kq+1],
                                     Whh[t*HIDD + 4*kq+2], Whh[t*HIDD + 4*kq+3]);
}

/* ============ kernel 1: fused edge-MLP + 4-head attention -> ctx ========
 * 128 threads = 2 independent 64-thread groups; thread = output channel o.
 * Q/V weights packed float4 over k in SMEM; edge rows read via LDS.128.   */
__global__ void __launch_bounds__(128) k_ctx(
    const float* __restrict__ seqs, const float* __restrict__ ets, const int* __restrict__ masks,
    const float* __restrict__ Wfus, const float* __restrict__ bfus,
    const float* __restrict__ Wk,   const float* __restrict__ bk,
    const float* __restrict__ Wq,   const float* __restrict__ bq,
    const float* __restrict__ Wv,   const float* __restrict__ bv)
{
    __shared__ __align__(16) float  s_fus[FIN*64];     /* [k][o] */
    __shared__ __align__(16) float4 s_wq4[16*64];      /* [kq][o] 4-k packed */
    __shared__ __align__(16) float4 s_wv4[16*64];
    __shared__ __align__(16) float  s_wk[6*64];
    __shared__ float s_bq[64], s_bv[64], s_bfus[64], s_bk[64];
    __shared__ __align__(16) float  s_edge[2][9*64];
    __shared__ __align__(16) float  s_raw[2][90];
    __shared__ int s_msk[2][9];

    const int tid = threadIdx.x;
    for (int i = tid; i < FIN*64; i += 128){ int k=i>>6, o=i&63; s_fus[i] = Wfus[o*FIN + k]; }
    for (int i = tid; i < 16*64; i += 128){
        int kq=i>>6, o=i&63;
        s_wq4[i] = make_float4(Wq[o*64+4*kq], Wq[o*64+4*kq+1], Wq[o*64+4*kq+2], Wq[o*64+4*kq+3]);
        s_wv4[i] = make_float4(Wv[o*64+4*kq], Wv[o*64+4*kq+1], Wv[o*64+4*kq+2], Wv[o*64+4*kq+3]);
    }
    for (int i = tid; i < 6*64; i += 128){ int k=i>>6, o=i&63; s_wk[i] = Wk[o*6 + k]; }
    if (tid < 64){ s_bq[tid]=bq[tid]; s_bv[tid]=bv[tid]; s_bfus[tid]=bfus[tid]; s_bk[tid]=bk[tid]; }
    __syncthreads();

    const int g   = tid >> 6;
    const int o   = tid & 63;
    const int bar = g + 1;                 /* named barrier id, 64 threads */
    const int ggid    = blockIdx.x*2 + g;
    const int ngroups = gridDim.x*2;

    for (int p = ggid; p < NP; p += ngroups){
        const float* sq = seqs + (size_t)p*54;
        const float* se = ets  + (size_t)p*36;
        for (int i = o; i < 90; i += 64) s_raw[g][i] = (i < 54) ? sq[i] : se[i-54];
        if (o < 9) s_msk[g][o] = masks[(size_t)p*9 + o];
        asm volatile("bar.sync %0, 64;" :: "r"(bar) : "memory");

        /* edge_info[n][o] = [seq(6),etype(4),onehot9] @ Wfus^T + bfus */
        float keyo;
        #pragma unroll
        for (int n = 0; n < 9; n++){
            float acc = s_bfus[o] + s_fus[(10+n)*64 + o];     /* one-hot loc */
            #pragma unroll
            for (int k = 0; k < 6; k++) acc += s_fus[k*64+o]     * s_raw[g][n*6+k];
            #pragma unroll
            for (int k = 0; k < 4; k++) acc += s_fus[(6+k)*64+o] * s_raw[g][54 + n*4 + k];
            s_edge[g][n*64 + o] = acc;
        }
        {   /* key from self (center cell n=4) */
            float acck = s_bk[o];
            #pragma unroll
            for (int k = 0; k < 6; k++) acck += s_wk[k*64+o] * s_raw[g][24 + k];
            keyo = acck;
        }
        asm volatile("bar.sync %0, 64;" :: "r"(bar) : "memory");

        /* Q,V: 9 slots x 64 cols, 4-k quads via LDS.128 */
        ull q2[9], v2[9];
        #pragma unroll
        for (int n = 0; n < 9; n++){ q2[n] = 0ULL; v2[n] = 0ULL; }
        #pragma unroll 4
        for (int kq = 0; kq < 16; kq++){
            ulonglong2 wq = *reinterpret_cast<const ulonglong2*>(&s_wq4[kq*64 + o]);
            ulonglong2 wv = *reinterpret_cast<const ulonglong2*>(&s_wv4[kq*64 + o]);
            #pragma unroll
            for (int n = 0; n < 9; n++){
                ulonglong2 e = *reinterpret_cast<const ulonglong2*>(&s_edge[g][n*64 + 4*kq]);
                fma2(q2[n], wq.x, e.x);
                fma2(q2[n], wq.y, e.y);
                fma2(v2[n], wv.x, e.x);
                fma2(v2[n], wv.y, e.y);
            }
        }

        /* attention: per-head (16-lane segment) dot + masked softmax over 9 */
        float a_att[9], vn[9];
        #pragma unroll
        for (int n = 0; n < 9; n++){
            float qn = hsum2(q2[n]) + s_bq[o];
            vn[n]    = hsum2(v2[n]) + s_bv[o];
            float part = keyo * qn;
            part += __shfl_xor_sync(0xffffffffu, part, 8);
            part += __shfl_xor_sync(0xffffffffu, part, 4);
            part += __shfl_xor_sync(0xffffffffu, part, 2);
            part += __shfl_xor_sync(0xffffffffu, part, 1);
            a_att[n] = (s_msk[g][n] == 0) ? -1e10f : part * 0.25f;  /* /sqrt(16) */
        }
        float m = a_att[0];
        #pragma unroll
        for (int n = 1; n < 9; n++) m = fmaxf(m, a_att[n]);
        float ssum = 0.f;
        #pragma unroll
        for (int n = 0; n < 9; n++){ a_att[n] = __expf(a_att[n] - m); ssum += a_att[n]; }
        float inv = 1.f / ssum;
        float ctx = 0.f;
        #pragma unroll
        for (int n = 0; n < 9; n++) ctx += a_att[n] * vn[n];
        ctx *= inv;

        int b = p / SEQL, s = p - b*SEQL;            /* time-major for LSTM */
        g_ctx[((size_t)s*BSZ + b)*ATTD + o] = ctx;
        asm volatile("bar.sync %0, 64;" :: "r"(bar) : "memory");
    }
}

/* ============ kernel 2: xg = ctx @ W_ih^T + (b_ih + b_hh) ================
 * Block = 128 threads, 128-wide gate-col tile, 16-row chunks.
 * Thread tile = 4 rows x 4 cols; all operands via 128-bit accesses.       */
__global__ void __launch_bounds__(128) k_xg(
    const float* __restrict__ Wih, const float* __restrict__ bih, const float* __restrict__ bhh)
{
    __shared__ __align__(16) float4 s_w4[16*128];  /* [kq][jj] 4-k packed, 32KB */
    __shared__ __align__(16) float  s_b[128];
    __shared__ __align__(16) float  s_c[16*64];    /* 16 ctx rows, 4KB */
    const int tid = threadIdx.x;
    const int jt  = blockIdx.x & 3;
    const int rb  = blockIdx.x >> 2;               /* 0..147 */
    const int cq  = tid & 31;                      /* col-quad: cols 4cq..4cq+3 */
    const int rq  = tid >> 5;                      /* row-quad: rows 4rq..4rq+3 */

    for (int i = tid; i < 16*128; i += 128){
        int kq = i >> 7, jj = i & 127, jg = jt*128 + jj;
        s_w4[i] = make_float4(Wih[jg*64 + 4*kq],   Wih[jg*64 + 4*kq+1],
                              Wih[jg*64 + 4*kq+2], Wih[jg*64 + 4*kq+3]);
    }
    s_b[tid] = bih[jt*128 + tid] + bhh[jt*128 + tid];
    __syncthreads();

    const float4 b4 = *reinterpret_cast<const float4*>(&s_b[4*cq]);

    for (int r0 = rb*16; r0 < NP; r0 += 148*16){   /* NP % 16 == 0 */
        {
            const float4* src = reinterpret_cast<const float4*>(g_ctx + (size_t)r0*64);
            float4* dst = reinterpret_cast<float4*>(s_c);
            dst[tid]       = src[tid];
            dst[tid + 128] = src[tid + 128];
        }
        __syncthreads();
        ull acc2[4][4];
        #pragma unroll
        for (int r = 0; r < 4; r++)
            #pragma unroll
            for (int c = 0; c < 4; c++) acc2[r][c] = 0ULL;
        #pragma unroll 4
        for (int kq = 0; kq < 16; kq++){
            ulonglong2 w[4], h[4];
            #pragma unroll
            for (int c = 0; c < 4; c++)
                w[c] = *reinterpret_cast<const ulonglong2*>(&s_w4[kq*128 + 4*cq + c]);
            #pragma unroll
            for (int r = 0; r < 4; r++)
                h[r] = *reinterpret_cast<const ulonglong2*>(&s_c[(4*rq + r)*64 + 4*kq]);
            #pragma unroll
            for (int r = 0; r < 4; r++)
                #pragma unroll
                for (int c = 0; c < 4; c++){
                    fma2(acc2[r][c], w[c].x, h[r].x);
                    fma2(acc2[r][c], w[c].y, h[r].y);
                }
        }
        #pragma unroll
        for (int r = 0; r < 4; r++){
            float4 out;
            out.x = hsum2(acc2[r][0]) + b4.x;
            out.y = hsum2(acc2[r][1]) + b4.y;
            out.z = hsum2(acc2[r][2]) + b4.z;
            out.w = hsum2(acc2[r][3]) + b4.w;
            *reinterpret_cast<float4*>(&g_xg[(size_t)(r0 + 4*rq + r)*G4 + jt*128 + 4*cq]) = out;
        }
        __syncthreads();
    }
}

/* ============ kernel 3: recurrent LSTM scan + output GEMM ================
 * 128 blocks x 512 threads; block owns 16 batch rows for all 50 steps.
 * Thread tile = 4 rows x 4 gate-cols; weights via coalesced LDG.128,
 * h via broadcast LDS.128: 8 loads per 32 fma2.                            */
__global__ void __launch_bounds__(512) k_lstm(
    const float* __restrict__ Wout, const float* __restrict__ bout, float* __restrict__ outp)
{
    __shared__ __align__(16) float s_h[16*HIDD];   /* 8 KB  */
    __shared__ __align__(16) float s_g[16*G4];     /* 32 KB */
    const int tid = threadIdx.x;
    const int b0  = blockIdx.x * 16;
    const int cq  = tid & 127;                     /* cols 4cq..4cq+3 */
    const int rq  = tid >> 7;                      /* rows 4rq..4rq+3 */
    for (int i = tid; i < 16*HIDD; i += 512) s_h[i] = 0.f;
    float creg[4] = {0.f, 0.f, 0.f, 0.f};
    __syncthreads();

    const ulonglong2* __restrict__ wp = reinterpret_cast<const ulonglong2*>(g_whh4t);

    for (int s = 0; s < SEQL; s++){
        ull acc2[4][4];
        #pragma unroll
        for (int r = 0; r < 4; r++)
            #pragma unroll
            for (int c = 0; c < 4; c++) acc2[r][c] = 0ULL;
        #pragma unroll 4
        for (int kq = 0; kq < 32; kq++){
            ulonglong2 w[4], h[4];
            #pragma unroll
            for (int c = 0; c < 4; c++) w[c] = wp[kq*G4 + 4*cq + c];      /* LDG.128 */
            #pragma unroll
            for (int r = 0; r < 4; r++)
                h[r] = *reinterpret_cast<const ulonglong2*>(&s_h[(4*rq + r)*HIDD + 4*kq]);
            #pragma unroll
            for (int r = 0; r < 4; r++)
                #pragma unroll
                for (int c = 0; c < 4; c++){
                    fma2(acc2[r][c], w[c].x, h[r].x);
                    fma2(acc2[r][c], w[c].y, h[r].y);
                }
        }
        const float* xgp = g_xg + ((size_t)s*BSZ + b0)*G4;
        #pragma unroll
        for (int r = 0; r < 4; r++){
            int rr = 4*rq + r;
            float4 xv = *reinterpret_cast<const float4*>(&xgp[(size_t)rr*G4 + 4*cq]);
            float4 out;
            out.x = hsum2(acc2[r][0]) + xv.x;
            out.y = hsum2(acc2[r][1]) + xv.y;
            out.z = hsum2(acc2[r][2]) + xv.z;
            out.w = hsum2(acc2[r][3]) + xv.w;
            *reinterpret_cast<float4*>(&s_g[rr*G4 + 4*cq]) = out;
        }
        __syncthreads();
        #pragma unroll
        for (int q = 0; q < 4; q++){                          /* 2048 cells / 512 thr */
            int cell = q*512 + tid;
            int r = cell >> 7, j = cell & 127;
            float ig = sigm(s_g[r*G4 + j]);
            float fg = sigm(s_g[r*G4 + 128 + j]);
            float gg = tanhfast(s_g[r*G4 + 256 + j]);
            float og = sigm(s_g[r*G4 + 384 + j]);
            float c  = fg*creg[q] + ig*gg;
            creg[q]  = c;
            s_h[r*HIDD + j] = og * tanhfast(c);
        }
        __syncthreads();
    }

    /* out = h_last @ W_out^T + b_out ; stage W_out^T in s_g (reuse) */
    float* s_wo = s_g;
    for (int i = tid; i < 64*HIDD; i += 512){
        int oo = i & 63, jj = i >> 6;
        s_wo[jj*64 + oo] = Wout[oo*HIDD + jj];
    }
    __syncthreads();
    #pragma unroll
    for (int q = 0; q < 2; q++){
        int cell = q*512 + tid;
        int r = cell >> 6, oo = cell & 63;
        float acc = __ldg(&bout[oo]);
        #pragma unroll 8
        for (int jj = 0; jj < HIDD; jj++) acc += s_wo[jj*64 + oo] * s_h[r*HIDD + jj];
        outp[(size_t)(b0 + r)*64 + oo] = acc;
    }
}

/* ======================================================================== */
extern "C" void kernel_launch(void* const* d_in, const int* in_sizes, int n_in,
                              void* d_out, int out_size)
{
    const float* seqs = (const float*)d_in[0];
    const float* ets  = (const float*)d_in[1];
    const int*   msk  = (const int*)  d_in[2];
    const float* Wfus = (const float*)d_in[3];
    const float* bfus = (const float*)d_in[4];
    const float* Wk   = (const float*)d_in[5];
    const float* bk   = (const float*)d_in[6];
    const float* Wq   = (const float*)d_in[7];
    const float* bq   = (const float*)d_in[8];
    const float* Wv   = (const float*)d_in[9];
    const float* bv   = (const float*)d_in[10];
    const float* Wih  = (const float*)d_in[11];
    const float* Whh  = (const float*)d_in[12];
    const float* bih  = (const float*)d_in[13];
    const float* bhh  = (const float*)d_in[14];
    const float* Wout = (const float*)d_in[15];
    const float* bout = (const float*)d_in[16];
    float* outp = (float*)d_out;

    k_pack<<<32, 512>>>(Whh);
    k_ctx <<<592, 128>>>(seqs, ets, msk, Wfus, bfus, Wk, bk, Wq, bq, Wv, bv);
    k_xg  <<<592, 128>>>(Wih, bih, bhh);
    k_lstm<<<128, 512>>>(Wout, bout, outp);
}

// round 4
// speedup vs baseline: 1.3825x; 1.3825x over previous
#include <cuda_runtime.h>

#define BSZ  2048
#define SEQL 50
#define NP   (BSZ*SEQL)      /* 102400 pairs */
#define ATTD 64
#define HIDD 128
#define G4   512             /* 4*HID gates */
#define FIN  19              /* 6 + 4 + 9 fused input dim */

typedef unsigned long long ull;

/* ---------------- device scratch (no cudaMalloc allowed) ---------------- */
__device__ float  g_ctx[(size_t)NP * ATTD];        /* [s][b][64]  26 MB  */
__device__ float  g_xg [(size_t)NP * G4];          /* [s][b][512] 210 MB */
__device__ float2 g_whh2t[(HIDD/2) * G4];          /* [kk][t] packed W_hh^T */

/* ---------------- f32x2 helpers (2 MACs / instr on sm_103a) ------------- */
__device__ __forceinline__ void fma2(ull& d, ull a, ull b){
    asm("fma.rn.f32x2 %0, %1, %2, %0;" : "+l"(d) : "l"(a), "l"(b));
}
__device__ __forceinline__ float2 unpk(ull v){
    float2 r; asm("mov.b64 {%0, %1}, %2;" : "=f"(r.x), "=f"(r.y) : "l"(v)); return r;
}
__device__ __forceinline__ float hsum2(ull v){ float2 f = unpk(v); return f.x + f.y; }
__device__ __forceinline__ float sigm(float x){ return 1.f/(1.f + __expf(-x)); }
__device__ __forceinline__ float tanhfast(float x){ return 1.f - 2.f/(__expf(2.f*x) + 1.f); }

/* ============ kernel 0: transpose+pack W_hh -> [kk][t] float2 =========== */
__global__ void k_pack(const float* __restrict__ Whh){
    int t = threadIdx.x, kk = blockIdx.x;             /* <<<64,512>>> */
    g_whh2t[kk*G4 + t] = make_float2(Whh[t*HIDD + 2*kk], Whh[t*HIDD + 2*kk+1]);
}

/* ============ kernel 1: fused edge-MLP + 4-head attention -> ctx ========
 * (round-1 proven version; conflict-free float2 weight layout)
 * smem ~45.6KB -> 5 blocks/SM; grid 740 = single full wave.               */
__global__ void __launch_bounds__(128) k_ctx(
    const float* __restrict__ seqs, const float* __restrict__ ets, const int* __restrict__ masks,
    const float* __restrict__ Wfus, const float* __restrict__ bfus,
    const float* __restrict__ Wk,   const float* __restrict__ bk,
    const float* __restrict__ Wq,   const float* __restrict__ bq,
    const float* __restrict__ Wv,   const float* __restrict__ bv)
{
    __shared__ __align__(16) float  s_fus[FIN*64];     /* [k][o] */
    __shared__ __align__(16) float2 s_wq2[32*64];      /* [kk][o] packed */
    __shared__ __align__(16) float2 s_wv2[32*64];
    __shared__ __align__(16) float  s_wk[6*64];
    __shared__ float s_bq[64], s_bv[64], s_bfus[64], s_bk[64];
    __shared__ __align__(16) float  s_edge[2][9*64];
    __shared__ __align__(16) float  s_raw[2][90];
    __shared__ int s_msk[2][9];

    const int tid = threadIdx.x;
    for (int i = tid; i < FIN*64; i += 128){ int k=i>>6, o=i&63; s_fus[i] = Wfus[o*FIN + k]; }
    for (int i = tid; i < 32*64; i += 128){
        int kk=i>>6, o=i&63;
        s_wq2[i] = make_float2(Wq[o*64+2*kk], Wq[o*64+2*kk+1]);
        s_wv2[i] = make_float2(Wv[o*64+2*kk], Wv[o*64+2*kk+1]);
    }
    for (int i = tid; i < 6*64; i += 128){ int k=i>>6, o=i&63; s_wk[i] = Wk[o*6 + k]; }
    if (tid < 64){ s_bq[tid]=bq[tid]; s_bv[tid]=bv[tid]; s_bfus[tid]=bfus[tid]; s_bk[tid]=bk[tid]; }
    __syncthreads();

    const int g   = tid >> 6;
    const int o   = tid & 63;
    const int bar = g + 1;                 /* named barrier id, 64 threads */
    const int ggid    = blockIdx.x*2 + g;
    const int ngroups = gridDim.x*2;

    for (int p = ggid; p < NP; p += ngroups){
        const float* sq = seqs + (size_t)p*54;
        const float* se = ets  + (size_t)p*36;
        for (int i = o; i < 90; i += 64) s_raw[g][i] = (i < 54) ? sq[i] : se[i-54];
        if (o < 9) s_msk[g][o] = masks[(size_t)p*9 + o];
        asm volatile("bar.sync %0, 64;" :: "r"(bar) : "memory");

        /* edge_info[n][o] = [seq(6),etype(4),onehot9] @ Wfus^T + bfus */
        float keyo;
        #pragma unroll
        for (int n = 0; n < 9; n++){
            float acc = s_bfus[o] + s_fus[(10+n)*64 + o];     /* one-hot loc */
            #pragma unroll
            for (int k = 0; k < 6; k++) acc += s_fus[k*64+o]     * s_raw[g][n*6+k];
            #pragma unroll
            for (int k = 0; k < 4; k++) acc += s_fus[(6+k)*64+o] * s_raw[g][54 + n*4 + k];
            s_edge[g][n*64 + o] = acc;
        }
        {   /* key from self (center cell n=4) */
            float acck = s_bk[o];
            #pragma unroll
            for (int k = 0; k < 6; k++) acck += s_wk[k*64+o] * s_raw[g][24 + k];
            keyo = acck;
        }
        asm volatile("bar.sync %0, 64;" :: "r"(bar) : "memory");

        /* Q,V: 9 slots x 64 cols, f32x2 packed over k */
        ull q2[9], v2[9];
        #pragma unroll
        for (int n = 0; n < 9; n++){ q2[n] = 0ULL; v2[n] = 0ULL; }
        #pragma unroll 4
        for (int kk = 0; kk < 32; kk++){
            ull wq = *reinterpret_cast<const ull*>(&s_wq2[kk*64 + o]);
            ull wv = *reinterpret_cast<const ull*>(&s_wv2[kk*64 + o]);
            #pragma unroll
            for (int n = 0; n < 9; n++){
                ull e2 = *reinterpret_cast<const ull*>(&s_edge[g][n*64 + 2*kk]);
                fma2(q2[n], wq, e2);
                fma2(v2[n], wv, e2);
            }
        }

        /* attention: per-head (16-lane segment) dot + masked softmax over 9 */
        float a_att[9], vn[9];
        #pragma unroll
        for (int n = 0; n < 9; n++){
            float qn = hsum2(q2[n]) + s_bq[o];
            vn[n]    = hsum2(v2[n]) + s_bv[o];
            float part = keyo * qn;
            part += __shfl_xor_sync(0xffffffffu, part, 8);
            part += __shfl_xor_sync(0xffffffffu, part, 4);
            part += __shfl_xor_sync(0xffffffffu, part, 2);
            part += __shfl_xor_sync(0xffffffffu, part, 1);
            a_att[n] = (s_msk[g][n] == 0) ? -1e10f : part * 0.25f;  /* /sqrt(16) */
        }
        float m = a_att[0];
        #pragma unroll
        for (int n = 1; n < 9; n++) m = fmaxf(m, a_att[n]);
        float ssum = 0.f;
        #pragma unroll
        for (int n = 0; n < 9; n++){ a_att[n] = __expf(a_att[n] - m); ssum += a_att[n]; }
        float inv = 1.f / ssum;
        float ctx = 0.f;
        #pragma unroll
        for (int n = 0; n < 9; n++) ctx += a_att[n] * vn[n];
        ctx *= inv;

        int b = p / SEQL, s = p - b*SEQL;            /* time-major for LSTM */
        g_ctx[((size_t)s*BSZ + b)*ATTD + o] = ctx;
        asm volatile("bar.sync %0, 64;" :: "r"(bar) : "memory");
    }
}

/* ============ kernel 2: xg = ctx @ W_ih^T + (b_ih + b_hh) ================
 * round-1 proven inner loop; smem ~37.4KB -> 6 blocks/SM; grid 888
 * (= 4 col-tiles x 222 row owners) = single full wave.                    */
__global__ void __launch_bounds__(128) k_xg(
    const float* __restrict__ Wih, const float* __restrict__ bih, const float* __restrict__ bhh)
{
    __shared__ __align__(16) float2 s_w2[32*128];  /* [kk][jj] packed over k */
    __shared__ float s_b[128];
    __shared__ __align__(16) float s_c[16*64];     /* 16 ctx rows */
    const int tid = threadIdx.x;
    const int jt  = blockIdx.x & 3;
    const int rb  = blockIdx.x >> 2;               /* 0..221 */
    const int j   = jt*128 + tid;

    for (int i = tid; i < 32*128; i += 128){
        int kk = i >> 7, jj = i & 127, jg = jt*128 + jj;
        s_w2[i] = make_float2(Wih[jg*64 + 2*kk], Wih[jg*64 + 2*kk + 1]);
    }
    s_b[tid] = bih[j] + bhh[j];
    __syncthreads();

    for (int r0 = rb*16; r0 < NP; r0 += 222*16){   /* NP % 16 == 0: full chunks */
        for (int i = tid; i < 16*64; i += 128) s_c[i] = g_ctx[(size_t)r0*64 + i];
        __syncthreads();
        ull acc2[16];
        #pragma unroll
        for (int r = 0; r < 16; r++) acc2[r] = 0ULL;
        #pragma unroll 4
        for (int kk = 0; kk < 32; kk++){
            ull w2 = *reinterpret_cast<const ull*>(&s_w2[kk*128 + tid]);
            #pragma unroll
            for (int r = 0; r < 16; r++){
                ull c2 = *reinterpret_cast<const ull*>(&s_c[r*64 + 2*kk]);
                fma2(acc2[r], w2, c2);
            }
        }
        float bj = s_b[tid];
        #pragma unroll
        for (int r = 0; r < 16; r++){
            g_xg[(size_t)(r0+r)*G4 + j] = hsum2(acc2[r]) + bj;
        }
        __syncthreads();
    }
}

/* ============ kernel 3: recurrent LSTM scan + output GEMM ================
 * 256 blocks x 512 threads; block owns 8 batch rows for all 50 steps.
 * 2 blocks/SM (36KB smem), zero idle SMs. Thread t owns gate col t;
 * weights coalesced LDG.64 (no duplication), h broadcast LDS.64.
 * NOTE: s_g sized for epilogue W_out^T staging (64*HIDD floats).          */
__global__ void __launch_bounds__(512) k_lstm(
    const float* __restrict__ Wout, const float* __restrict__ bout, float* __restrict__ outp)
{
    __shared__ __align__(16) float s_h[8*HIDD];    /* 4 KB  */
    __shared__ __align__(16) float s_g[64*HIDD];   /* 32 KB: gates need 8*G4=4096,
                                                      epilogue needs 64*128=8192 */
    const int tid = threadIdx.x;
    const int b0  = blockIdx.x * 8;
    for (int i = tid; i < 8*HIDD; i += 512) s_h[i] = 0.f;
    float creg[2] = {0.f, 0.f};
    __syncthreads();

    const ull* __restrict__ wp = reinterpret_cast<const ull*>(g_whh2t);

    for (int s = 0; s < SEQL; s++){
        ull acc2[8];
        #pragma unroll
        for (int r = 0; r < 8; r++) acc2[r] = 0ULL;
        #pragma unroll 8
        for (int kk = 0; kk < 64; kk++){
            ull w2 = __ldg(&wp[kk*G4 + tid]);               /* coalesced */
            #pragma unroll
            for (int r = 0; r < 8; r++){
                ull h2 = *reinterpret_cast<const ull*>(&s_h[r*HIDD + 2*kk]);
                fma2(acc2[r], w2, h2);
            }
        }
        const float* xgp = g_xg + ((size_t)s*BSZ + b0)*G4;
        #pragma unroll
        for (int r = 0; r < 8; r++){
            s_g[r*G4 + tid] = hsum2(acc2[r]) + __ldg(&xgp[r*G4 + tid]);
        }
        __syncthreads();
        #pragma unroll
        for (int q = 0; q < 2; q++){                        /* 1024 cells / 512 thr */
            int cell = q*512 + tid;
            int r = cell >> 7, j = cell & 127;
            float ig = sigm(s_g[r*G4 + j]);
            float fg = sigm(s_g[r*G4 + 128 + j]);
            float gg = tanhfast(s_g[r*G4 + 256 + j]);
            float og = sigm(s_g[r*G4 + 384 + j]);
            float c  = fg*creg[q] + ig*gg;
            creg[q]  = c;
            s_h[r*HIDD + j] = og * tanhfast(c);
        }
        __syncthreads();
    }

    /* out = h_last @ W_out^T + b_out ; stage W_out^T [jj][oo] in s_g */
    float* s_wo = s_g;
    for (int i = tid; i < 64*HIDD; i += 512){
        int oo = i & 63, jj = i >> 6;
        s_wo[jj*64 + oo] = Wout[oo*HIDD + jj];
    }
    __syncthreads();
    {
        int r = tid >> 6, oo = tid & 63;                    /* 8 rows x 64 cols */
        float acc = __ldg(&bout[oo]);
        #pragma unroll 8
        for (int jj = 0; jj < HIDD; jj++) acc += s_wo[jj*64 + oo] * s_h[r*HIDD + jj];
        outp[(size_t)(b0 + r)*64 + oo] = acc;
    }
}

/* ======================================================================== */
extern "C" void kernel_launch(void* const* d_in, const int* in_sizes, int n_in,
                              void* d_out, int out_size)
{
    const float* seqs = (const float*)d_in[0];
    const float* ets  = (const float*)d_in[1];
    const int*   msk  = (const int*)  d_in[2];
    const float* Wfus = (const float*)d_in[3];
    const float* bfus = (const float*)d_in[4];
    const float* Wk   = (const float*)d_in[5];
    const float* bk   = (const float*)d_in[6];
    const float* Wq   = (const float*)d_in[7];
    const float* bq   = (const float*)d_in[8];
    const float* Wv   = (const float*)d_in[9];
    const float* bv   = (const float*)d_in[10];
    const float* Wih  = (const float*)d_in[11];
    const float* Whh  = (const float*)d_in[12];
    const float* bih  = (const float*)d_in[13];
    const float* bhh  = (const float*)d_in[14];
    const float* Wout = (const float*)d_in[15];
    const float* bout = (const float*)d_in[16];
    float* outp = (float*)d_out;

    k_pack<<<64, 512>>>(Whh);
    k_ctx <<<740, 128>>>(seqs, ets, msk, Wfus, bfus, Wk, bk, Wq, bq, Wv, bv);
    k_xg  <<<888, 128>>>(Wih, bih, bhh);
    k_lstm<<<256, 512>>>(Wout, bout, outp);
}